// round 1
// baseline (speedup 1.0000x reference)
#include <cuda_runtime.h>
#include <math.h>

#define ZBATCH 16
#define ZD 256
#define ZT 4096
#define NVEC (ZBATCH*ZT)          // 65536 vectors
#define NELEM (ZBATCH*ZD*ZT)      // 16777216 output tensor elements
#define NCODE 1024

#define BM 128
#define BN 128
#define BK 16
#define TM 8
#define TN 8
#define BSN 132                    // padded Bs row to dodge STS bank conflicts

#define ARGMIN_SMEM ((ZD*BM + BK*BSN) * 4)   // 139,520 bytes

// ---------------- scratch (device globals; no allocation allowed) ----------
__device__ int          g_idx[NVEC];
__device__ unsigned int g_hist[NCODE];
__device__ float        g_enorm[NCODE];
__device__ double       g_loss;

// ---------------- kernel 0: per-launch scratch reset -----------------------
__global__ void vq_init_kernel() {
    int t = threadIdx.x;
    if (t < NCODE) g_hist[t] = 0u;
    if (t == 0)    g_loss = 0.0;
}

// ---------------- kernel 1: ||e_c||^2 per code -----------------------------
__global__ void vq_enorm_kernel(const float* __restrict__ emb) {
    int gw   = (blockIdx.x * blockDim.x + threadIdx.x) >> 5;
    int lane = threadIdx.x & 31;
    int nw   = (gridDim.x * blockDim.x) >> 5;
    for (int c = gw; c < NCODE; c += nw) {
        const float* row = emb + (size_t)c * ZD;
        float s = 0.f;
        #pragma unroll
        for (int k = lane; k < ZD; k += 32) { float v = row[k]; s = fmaf(v, v, s); }
        #pragma unroll
        for (int o = 16; o > 0; o >>= 1) s += __shfl_down_sync(0xffffffffu, s, o);
        if (lane == 0) g_enorm[c] = s;
    }
}

// ---------------- kernel 2: GEMM + argmin epilogue -------------------------
// block: 256 threads (16x16), tile BM=128 vectors x BN=128 codes, full K=256.
// A tile (z) resident in smem for the whole block; E streamed in BK chunks.
extern __shared__ float smem[];

__global__ __launch_bounds__(256, 1)
void vq_argmin_kernel(const float* __restrict__ z, const float* __restrict__ emb) {
    float* As = smem;               // [256][128]  z tile, k-major
    float* Bs = smem + ZD * BM;     // [BK][BSN]   e chunk

    int tid = threadIdx.x;
    int tx  = tid & 15;             // code sub-tile
    int ty  = tid >> 4;             // vector sub-tile

    int n0 = blockIdx.x * BM;       // first vector of this block
    int b  = n0 / ZT;               // ZT % BM == 0 -> whole tile in one batch
    int t0 = n0 % ZT;
    const float* zb = z + (size_t)b * ZD * ZT + t0;

    // load full A tile: As[k][m] = z[b, k, t0+m]   (coalesced float4 along m)
    for (int i = tid; i < ZD * BM / 4; i += 256) {
        int k  = i >> 5;
        int m4 = i & 31;
        *(float4*)(As + k * BM + m4 * 4) =
            *(const float4*)(zb + (size_t)k * ZT + m4 * 4);
    }

    float bestd[TM];
    int   bestc[TM];
    #pragma unroll
    for (int i = 0; i < TM; i++) { bestd[i] = 3.4e38f; bestc[i] = 0; }

    for (int ct = 0; ct < NCODE / BN; ct++) {
        float acc[TM][TN];
        #pragma unroll
        for (int i = 0; i < TM; i++)
            #pragma unroll
            for (int j = 0; j < TN; j++) acc[i][j] = 0.f;

        for (int k0 = 0; k0 < ZD; k0 += BK) {
            __syncthreads();
            // load Bs[kk][nn] = emb[ct*BN+nn][k0+kk]  (kk fastest -> coalesced)
            for (int i = tid; i < BK * BN; i += 256) {
                int nn = i >> 4;
                int kk = i & 15;
                Bs[kk * BSN + nn] = emb[(size_t)(ct * BN + nn) * ZD + k0 + kk];
            }
            __syncthreads();

            #pragma unroll
            for (int kk = 0; kk < BK; kk++) {
                const float* arow = As + (k0 + kk) * BM + ty * TM;
                const float* brow = Bs + kk * BSN + tx * TN;
                float4 a0 = *(const float4*)(arow);
                float4 a1 = *(const float4*)(arow + 4);
                float4 b0 = *(const float4*)(brow);
                float4 b1 = *(const float4*)(brow + 4);
                float am[TM] = {a0.x, a0.y, a0.z, a0.w, a1.x, a1.y, a1.z, a1.w};
                float bn[TN] = {b0.x, b0.y, b0.z, b0.w, b1.x, b1.y, b1.z, b1.w};
                #pragma unroll
                for (int i = 0; i < TM; i++)
                    #pragma unroll
                    for (int j = 0; j < TN; j++)
                        acc[i][j] = fmaf(am[i], bn[j], acc[i][j]);
            }
        }

        // epilogue: dist = ||e||^2 - 2*dot ; strict < keeps first (lowest c)
        #pragma unroll
        for (int j = 0; j < TN; j++) {
            int c = ct * BN + tx * TN + j;
            float en = __ldg(&g_enorm[c]);
            #pragma unroll
            for (int i = 0; i < TM; i++) {
                float dist = fmaf(-2.f, acc[i][j], en);
                if (dist < bestd[i]) { bestd[i] = dist; bestc[i] = c; }
            }
        }
    }

    // cross-thread (tx) reduction per vector row, first-min tie-break by scan order
    __syncthreads();
    float* redD = smem;                        // [128][16] floats
    int*   redC = (int*)(smem + BM * 16);      // [128][16] ints
    #pragma unroll
    for (int i = 0; i < TM; i++) {
        int r = ty * TM + i;
        redD[r * 16 + tx] = bestd[i];
        redC[r * 16 + tx] = bestc[i];
    }
    __syncthreads();
    if (tid < BM) {
        float bd = 3.4e38f; int bc = 0;
        #pragma unroll
        for (int x = 0; x < 16; x++) {
            float d = redD[tid * 16 + x];
            int   c = redC[tid * 16 + x];
            if (d < bd) { bd = d; bc = c; }   // x scan == ascending c
        }
        g_idx[n0 + tid] = bc;
        atomicAdd(&g_hist[bc], 1u);
    }
}

// ---------------- kernel 3: gather + output + loss -------------------------
__global__ __launch_bounds__(256)
void vq_gather_kernel(const float* __restrict__ z, const float* __restrict__ emb,
                      float* __restrict__ out) {
    int g = blockIdx.x * blockDim.x + threadIdx.x;   // float4 group over (b,d,t)
    float lsum = 0.f;
    {
        int base = g * 4;
        int t  = base % ZT;
        int bd = base / ZT;
        int d  = bd % ZD;
        int b  = bd / ZD;
        int nb = b * ZT + t;
        float4 zv = *(const float4*)(z + (size_t)base);
        float4 ev;
        ev.x = __ldg(&emb[(size_t)g_idx[nb + 0] * ZD + d]);
        ev.y = __ldg(&emb[(size_t)g_idx[nb + 1] * ZD + d]);
        ev.z = __ldg(&emb[(size_t)g_idx[nb + 2] * ZD + d]);
        ev.w = __ldg(&emb[(size_t)g_idx[nb + 3] * ZD + d]);
        *(float4*)(out + (size_t)base) = ev;
        float dx = zv.x - ev.x, dy = zv.y - ev.y;
        float dz = zv.z - ev.z, dw = zv.w - ev.w;
        lsum = dx*dx + dy*dy + dz*dz + dw*dw;
    }
    // block reduce
    __shared__ float warpsum[8];
    int lane = threadIdx.x & 31, wid = threadIdx.x >> 5;
    #pragma unroll
    for (int o = 16; o > 0; o >>= 1) lsum += __shfl_down_sync(0xffffffffu, lsum, o);
    if (lane == 0) warpsum[wid] = lsum;
    __syncthreads();
    if (wid == 0) {
        float s = (lane < 8) ? warpsum[lane] : 0.f;
        #pragma unroll
        for (int o = 4; o > 0; o >>= 1) s += __shfl_down_sync(0xffffffffu, s, o);
        if (lane == 0) atomicAdd(&g_loss, (double)s);
    }
}

// ---------------- kernel 4: perplexity + scalar outputs --------------------
__global__ void vq_finalize_kernel(float* __restrict__ out, int out_size) {
    __shared__ float warpsum[32];
    int t = threadIdx.x;                       // 1024 threads == NCODE
    float p = (float)g_hist[t] / (float)NVEC;
    float term = p * logf(p + 1e-10f);
    int lane = t & 31, wid = t >> 5;
    #pragma unroll
    for (int o = 16; o > 0; o >>= 1) term += __shfl_down_sync(0xffffffffu, term, o);
    if (lane == 0) warpsum[wid] = term;
    __syncthreads();
    if (wid == 0) {
        float s = warpsum[lane];
        #pragma unroll
        for (int o = 16; o > 0; o >>= 1) s += __shfl_down_sync(0xffffffffu, s, o);
        if (lane == 0) {
            float perp = expf(-s);
            float loss = (float)g_loss;
            out[out_size - 3] = loss;   // z_qut_loss
            out[out_size - 2] = loss;   // z_enc_loss (identical numerically)
            out[out_size - 1] = perp;
        }
    }
}

// ---------------- launcher -------------------------------------------------
extern "C" void kernel_launch(void* const* d_in, const int* in_sizes, int n_in,
                              void* d_out, int out_size) {
    const float* z   = (const float*)d_in[0];
    const float* emb = (const float*)d_in[1];
    if (n_in >= 2 && in_sizes[0] == NCODE * ZD && in_sizes[1] == NELEM) {
        // defensive: inputs swapped in metadata order
        const float* tmp = z; z = emb; emb = tmp;
    }
    float* out = (float*)d_out;

    cudaFuncSetAttribute(vq_argmin_kernel,
                         cudaFuncAttributeMaxDynamicSharedMemorySize, ARGMIN_SMEM);

    vq_init_kernel<<<1, 1024>>>();
    vq_enorm_kernel<<<32, 256>>>(emb);
    vq_argmin_kernel<<<NVEC / BM, 256, ARGMIN_SMEM>>>(z, emb);
    vq_gather_kernel<<<(NELEM / 4) / 256, 256>>>(z, emb, out);
    vq_finalize_kernel<<<1, 1024>>>(out, out_size);
}

// round 5
// speedup vs baseline: 2.6372x; 2.6372x over previous
#include <cuda_runtime.h>
#include <cuda_bf16.h>
#include <stdint.h>
#include <math.h>

#define ZB   16
#define ZD   256
#define ZT   4096
#define NVEC (ZB*ZT)            // 65536
#define NELEM (ZB*ZD*ZT)        // 16777216
#define NCODE 1024

// ---------------- HMMA argmin tiling ---------------------------------------
// CTA: 256 thr (8 warps, 2(M) x 4(N)). Tile: 128 vectors x 128 codes.
// A (z tile, bf16 hi/lo) fully K-resident in smem; B (codebook chunk)
// cp.async double-buffered, BK=32 per chunk.
#define TILE_M 128
#define TILE_N 128
#define BK     32
#define NT_TILES (NCODE/TILE_N)   // 8
#define KCH      (ZD/BK)          // 8
#define NITER    (NT_TILES*KCH)   // 64

// A row stride: 264 bf16 = 528 B (132 words == 4 mod 32 -> conflict-free frags)
#define STRA_E 264
#define STRA_B (STRA_E*2)
#define A_H_OFF 0
#define A_L_OFF (TILE_M*STRA_B)            // 67584
// B: row stride 40 bf16 = 80 B (20 words -> conflict-free frags)
#define STRB_B 80
#define B_HL   (TILE_N*STRB_B)             // 10240
#define B_BUF  (2*B_HL)                    // 20480
#define B_BASE (2*TILE_M*STRA_B)           // 135168
#define RED_D  (B_BASE + 2*B_BUF)          // 176128
#define RED_C  (RED_D + TILE_M*4*4)        // +2048
#define SMEM_TOTAL (RED_C + TILE_M*4*4)    // 180224

// ---------------- scratch --------------------------------------------------
// 16B alignment is REQUIRED: cp.async.cg 16 on these as global source.
__device__ __align__(16) __nv_bfloat16 g_eh[NCODE*ZD];
__device__ __align__(16) __nv_bfloat16 g_el[NCODE*ZD];
__device__ int           g_idx[NVEC];
__device__ unsigned int  g_hist[NCODE];
__device__ float         g_enorm[NCODE];
__device__ double        g_loss;

// ---------------- helpers --------------------------------------------------
__device__ __forceinline__ void mma_bf16(float c[4], uint32_t a0, uint32_t a1,
                                         uint32_t a2, uint32_t a3,
                                         uint32_t b0, uint32_t b1) {
    asm volatile(
        "mma.sync.aligned.m16n8k16.row.col.f32.bf16.bf16.f32 "
        "{%0,%1,%2,%3}, {%4,%5,%6,%7}, {%8,%9}, {%0,%1,%2,%3};"
        : "+f"(c[0]), "+f"(c[1]), "+f"(c[2]), "+f"(c[3])
        : "r"(a0), "r"(a1), "r"(a2), "r"(a3), "r"(b0), "r"(b1));
}
#define CP_ASYNC16(dst, src) \
    asm volatile("cp.async.cg.shared.global [%0], [%1], 16;" :: "r"(dst), "l"(src))
#define CP_COMMIT() asm volatile("cp.async.commit_group;" ::: "memory")
#define CP_WAIT1()  asm volatile("cp.async.wait_group 1;" ::: "memory")

__device__ __forceinline__ uint32_t smem_u32(const void* p) {
    uint32_t a;
    asm("{ .reg .u64 t; cvta.to.shared.u64 t, %1; cvt.u32.u64 %0, t; }" : "=r"(a) : "l"(p));
    return a;
}

// ---------------- kernel 0: scratch reset ----------------------------------
__global__ void vq_init_kernel() {
    int t = threadIdx.x;
    if (t < NCODE) g_hist[t] = 0u;
    if (t == 0)    g_loss = 0.0;
}

// ---------------- kernel 1: codebook bf16 split + ||e||^2 ------------------
__global__ __launch_bounds__(256) void vq_embprep(const float* __restrict__ emb) {
    int c = blockIdx.x, d = threadIdx.x;
    float v = emb[(size_t)c * ZD + d];
    __nv_bfloat16 h = __float2bfloat16_rn(v);
    float hf = __bfloat162float(h);
    __nv_bfloat16 l = __float2bfloat16_rn(v - hf);
    g_eh[(size_t)c * ZD + d] = h;
    g_el[(size_t)c * ZD + d] = l;

    float s = v * v;
    __shared__ float ws[8];
    int lane = d & 31, w = d >> 5;
    #pragma unroll
    for (int o = 16; o > 0; o >>= 1) s += __shfl_down_sync(0xffffffffu, s, o);
    if (lane == 0) ws[w] = s;
    __syncthreads();
    if (d == 0) {
        float t2 = 0.f;
        #pragma unroll
        for (int i = 0; i < 8; i++) t2 += ws[i];
        g_enorm[c] = t2;
    }
}

// ---------------- kernel 2: HMMA bf16x3 GEMM + argmin ----------------------
extern __shared__ char smem[];

__device__ __forceinline__ void prefetch_chunk(int it2, int buf, int tid) {
    int nt = it2 >> 3, kc = it2 & 7;
    #pragma unroll
    for (int q = 0; q < 4; q++) {
        int idx = tid + q * 256;            // 0..1023
        int hl  = idx >> 9;                 // 0: hi, 1: lo
        int row = (idx >> 2) & 127;
        int seg = idx & 3;
        const __nv_bfloat16* src =
            (hl ? g_el : g_eh) + ((size_t)(nt * TILE_N + row) * ZD + kc * BK + seg * 8);
        uint32_t dst = smem_u32(smem) + B_BASE + buf * B_BUF + hl * B_HL
                     + row * STRB_B + seg * 16;
        CP_ASYNC16(dst, src);
    }
}

__global__ __launch_bounds__(256, 1)
void vq_argmin_mma(const float* __restrict__ z) {
    int tid = threadIdx.x, lane = tid & 31, wid = tid >> 5;
    int g = lane >> 2, t4 = lane & 3;
    int wm = wid & 1, wn = wid >> 1;

    int n0 = blockIdx.x * TILE_M;
    int b  = n0 / ZT, t0 = n0 % ZT;
    const float* zb = z + (size_t)b * ZD * ZT + t0;

    // ---- load + convert A tile (z) into padded hi/lo bf16 -----------------
    #pragma unroll 1
    for (int itl = 0; itl < 16; itl++) {
        int i  = tid + itl * 256;       // 0..4095
        int r  = i & 127;               // vector row
        int kq = i >> 7;                // 8-dim group 0..31
        union { __nv_bfloat16 h[8]; uint4 u; } H, L;
        #pragma unroll
        for (int j = 0; j < 8; j++) {
            float v = zb[(size_t)(kq * 8 + j) * ZT + r];
            __nv_bfloat16 hh = __float2bfloat16_rn(v);
            H.h[j] = hh;
            L.h[j] = __float2bfloat16_rn(v - __bfloat162float(hh));
        }
        uint32_t off = (uint32_t)(r * STRA_B + kq * 16);
        *(uint4*)(smem + A_H_OFF + off) = H.u;
        *(uint4*)(smem + A_L_OFF + off) = L.u;
    }

    // prologue: prefetch chunk 0 into buf 0
    prefetch_chunk(0, 0, tid);
    CP_COMMIT();
    __syncthreads();

    float c[4][4][4];
    #pragma unroll
    for (int i = 0; i < 4; i++)
        #pragma unroll
        for (int j = 0; j < 4; j++)
            #pragma unroll
            for (int r = 0; r < 4; r++) c[i][j][r] = 0.f;

    float bd[4][2];
    int   bc[4][2];
    #pragma unroll
    for (int i = 0; i < 4; i++) { bd[i][0] = bd[i][1] = 3.4e38f; bc[i][0] = bc[i][1] = 0; }

    #pragma unroll 1
    for (int it = 0; it < NITER; it++) {
        int nt  = it >> 3, kc = it & 7;
        int buf = it & 1;
        if (it + 1 < NITER) prefetch_chunk(it + 1, buf ^ 1, tid);
        CP_COMMIT();
        CP_WAIT1();
        __syncthreads();

        const char* Bh = smem + B_BASE + buf * B_BUF;
        const char* Bl = Bh + B_HL;

        #pragma unroll
        for (int ks = 0; ks < 2; ks++) {
            int kb = kc * BK + ks * 16;
            uint32_t ah[4][4], al[4][4], bh[4][2], bl[4][2];
            // A-hi fragments
            #pragma unroll
            for (int i = 0; i < 4; i++) {
                int m0 = wm * 64 + i * 16 + g;
                const char* base = smem + A_H_OFF + m0 * STRA_B + (kb + 2 * t4) * 2;
                ah[i][0] = *(const uint32_t*)(base);
                ah[i][1] = *(const uint32_t*)(base + 8 * STRA_B);
                ah[i][2] = *(const uint32_t*)(base + 16);
                ah[i][3] = *(const uint32_t*)(base + 8 * STRA_B + 16);
            }
            // B-hi fragments
            #pragma unroll
            for (int j = 0; j < 4; j++) {
                int row = wn * 32 + j * 8 + g;
                const char* base = Bh + row * STRB_B + (ks * 16 + 2 * t4) * 2;
                bh[j][0] = *(const uint32_t*)(base);
                bh[j][1] = *(const uint32_t*)(base + 16);
            }
            // pass 1: Ah * Bh
            #pragma unroll
            for (int i = 0; i < 4; i++)
                #pragma unroll
                for (int j = 0; j < 4; j++)
                    mma_bf16(c[i][j], ah[i][0], ah[i][1], ah[i][2], ah[i][3],
                             bh[j][0], bh[j][1]);
            // B-lo fragments, pass 2: Ah * Bl
            #pragma unroll
            for (int j = 0; j < 4; j++) {
                int row = wn * 32 + j * 8 + g;
                const char* base = Bl + row * STRB_B + (ks * 16 + 2 * t4) * 2;
                bl[j][0] = *(const uint32_t*)(base);
                bl[j][1] = *(const uint32_t*)(base + 16);
            }
            #pragma unroll
            for (int i = 0; i < 4; i++)
                #pragma unroll
                for (int j = 0; j < 4; j++)
                    mma_bf16(c[i][j], ah[i][0], ah[i][1], ah[i][2], ah[i][3],
                             bl[j][0], bl[j][1]);
            // A-lo fragments, pass 3: Al * Bh
            #pragma unroll
            for (int i = 0; i < 4; i++) {
                int m0 = wm * 64 + i * 16 + g;
                const char* base = smem + A_L_OFF + m0 * STRA_B + (kb + 2 * t4) * 2;
                al[i][0] = *(const uint32_t*)(base);
                al[i][1] = *(const uint32_t*)(base + 8 * STRA_B);
                al[i][2] = *(const uint32_t*)(base + 16);
                al[i][3] = *(const uint32_t*)(base + 8 * STRA_B + 16);
            }
            #pragma unroll
            for (int i = 0; i < 4; i++)
                #pragma unroll
                for (int j = 0; j < 4; j++)
                    mma_bf16(c[i][j], al[i][0], al[i][1], al[i][2], al[i][3],
                             bh[j][0], bh[j][1]);
        }

        if (kc == KCH - 1) {
            // fold tile nt into running per-row argmin; reset accumulators
            #pragma unroll
            for (int j = 0; j < 4; j++) {
                int col0 = nt * TILE_N + wn * 32 + j * 8 + 2 * t4;
                float e0 = __ldg(&g_enorm[col0]);
                float e1 = __ldg(&g_enorm[col0 + 1]);
                #pragma unroll
                for (int i = 0; i < 4; i++) {
                    float d0 = fmaf(-2.f, c[i][j][0], e0);
                    float d1 = fmaf(-2.f, c[i][j][1], e1);
                    float d2 = fmaf(-2.f, c[i][j][2], e0);
                    float d3 = fmaf(-2.f, c[i][j][3], e1);
                    if (d0 < bd[i][0] || (d0 == bd[i][0] && col0     < bc[i][0])) { bd[i][0] = d0; bc[i][0] = col0;     }
                    if (d1 < bd[i][0] || (d1 == bd[i][0] && col0 + 1 < bc[i][0])) { bd[i][0] = d1; bc[i][0] = col0 + 1; }
                    if (d2 < bd[i][1] || (d2 == bd[i][1] && col0     < bc[i][1])) { bd[i][1] = d2; bc[i][1] = col0;     }
                    if (d3 < bd[i][1] || (d3 == bd[i][1] && col0 + 1 < bc[i][1])) { bd[i][1] = d3; bc[i][1] = col0 + 1; }
                    c[i][j][0] = c[i][j][1] = c[i][j][2] = c[i][j][3] = 0.f;
                }
            }
        }
        __syncthreads();
    }

    // ---- quad (n-lane) reduce, then cross-warp reduce ---------------------
    #pragma unroll
    for (int i = 0; i < 4; i++)
        #pragma unroll
        for (int h = 0; h < 2; h++) {
            #pragma unroll
            for (int sh = 1; sh <= 2; sh <<= 1) {
                float od = __shfl_xor_sync(0xffffffffu, bd[i][h], sh);
                int   oc = __shfl_xor_sync(0xffffffffu, bc[i][h], sh);
                if (od < bd[i][h] || (od == bd[i][h] && oc < bc[i][h])) {
                    bd[i][h] = od; bc[i][h] = oc;
                }
            }
        }
    float* redD = (float*)(smem + RED_D);
    int*   redC = (int*)(smem + RED_C);
    if (t4 == 0) {
        #pragma unroll
        for (int i = 0; i < 4; i++)
            #pragma unroll
            for (int h = 0; h < 2; h++) {
                int row = wm * 64 + i * 16 + g + h * 8;
                redD[row * 4 + wn] = bd[i][h];
                redC[row * 4 + wn] = bc[i][h];
            }
    }
    __syncthreads();
    if (tid < TILE_M) {
        float fb = redD[tid * 4];
        int   fc = redC[tid * 4];
        #pragma unroll
        for (int w = 1; w < 4; w++) {
            float d = redD[tid * 4 + w];
            int   cc = redC[tid * 4 + w];
            if (d < fb || (d == fb && cc < fc)) { fb = d; fc = cc; }
        }
        g_idx[n0 + tid] = fc;
        atomicAdd(&g_hist[fc], 1u);
    }
}

// ---------------- kernel 3: coalesced gather + output + loss ---------------
__global__ __launch_bounds__(256)
void vq_gather_kernel(const float* __restrict__ z, const float* __restrict__ emb,
                      float* __restrict__ out) {
    __shared__ int   sidx[32];
    __shared__ float sE[32][257];
    int tid = threadIdx.x;
    int b   = blockIdx.x >> 7;
    int t0  = (blockIdx.x & 127) * 32;

    if (tid < 32) sidx[tid] = g_idx[b * ZT + t0 + tid];
    __syncthreads();

    {
        int r = tid >> 3;
        const float* row = emb + (size_t)sidx[r] * ZD;
        #pragma unroll
        for (int q = 0; q < 8; q++) {
            int c4 = (tid & 7) + q * 8;
            float4 v = *(const float4*)(row + c4 * 4);
            sE[r][c4 * 4 + 0] = v.x;
            sE[r][c4 * 4 + 1] = v.y;
            sE[r][c4 * 4 + 2] = v.z;
            sE[r][c4 * 4 + 3] = v.w;
        }
    }
    __syncthreads();

    float lsum = 0.f;
    int w = tid >> 5, lane = tid & 31;
    #pragma unroll 4
    for (int d = w; d < ZD; d += 8) {
        float e = sE[lane][d];
        size_t off = ((size_t)(b * ZD + d)) * ZT + t0 + lane;
        float zv = z[off];
        out[off] = e;
        float df = zv - e;
        lsum = fmaf(df, df, lsum);
    }

    __shared__ float ws[8];
    #pragma unroll
    for (int o = 16; o > 0; o >>= 1) lsum += __shfl_down_sync(0xffffffffu, lsum, o);
    if (lane == 0) ws[w] = lsum;
    __syncthreads();
    if (w == 0) {
        float s = (lane < 8) ? ws[lane] : 0.f;
        #pragma unroll
        for (int o = 4; o > 0; o >>= 1) s += __shfl_down_sync(0xffffffffu, s, o);
        if (lane == 0) atomicAdd(&g_loss, (double)s);
    }
}

// ---------------- kernel 4: perplexity + scalar outputs --------------------
__global__ void vq_finalize_kernel(float* __restrict__ out, int out_size) {
    __shared__ float warpsum[32];
    int t = threadIdx.x;
    float p = (float)g_hist[t] / (float)NVEC;
    float term = p * logf(p + 1e-10f);
    int lane = t & 31, w = t >> 5;
    #pragma unroll
    for (int o = 16; o > 0; o >>= 1) term += __shfl_down_sync(0xffffffffu, term, o);
    if (lane == 0) warpsum[w] = term;
    __syncthreads();
    if (w == 0) {
        float s = warpsum[lane];
        #pragma unroll
        for (int o = 16; o > 0; o >>= 1) s += __shfl_down_sync(0xffffffffu, s, o);
        if (lane == 0) {
            float perp = expf(-s);
            float loss = (float)g_loss;
            out[out_size - 3] = loss;
            out[out_size - 2] = loss;
            out[out_size - 1] = perp;
        }
    }
}

// ---------------- launcher -------------------------------------------------
extern "C" void kernel_launch(void* const* d_in, const int* in_sizes, int n_in,
                              void* d_out, int out_size) {
    const float* z   = (const float*)d_in[0];
    const float* emb = (const float*)d_in[1];
    if (n_in >= 2 && in_sizes[0] == NCODE * ZD && in_sizes[1] == NELEM) {
        const float* tmp = z; z = emb; emb = tmp;
    }
    float* out = (float*)d_out;

    cudaFuncSetAttribute(vq_argmin_mma,
                         cudaFuncAttributeMaxDynamicSharedMemorySize, SMEM_TOTAL);

    vq_init_kernel<<<1, 1024>>>();
    vq_embprep<<<NCODE, 256>>>(emb);
    vq_argmin_mma<<<NVEC / TILE_M, 256, SMEM_TOTAL>>>(z);
    vq_gather_kernel<<<ZB * (ZT / 32), 256>>>(z, emb, out);
    vq_finalize_kernel<<<1, 1024>>>(out, out_size);
}